// round 10
// baseline (speedup 1.0000x reference)
#include <cuda_runtime.h>
#include <math.h>

// Fixed-shape problem: B=4096, V=32000, fp32
#define VDIM   32000
#define NV4    (VDIM / 4)      // 8000
#define BMAX   4096
#define ATHR   256             // fused kernel threads (8 warps)
#define NWARP_A (ATHR / 32)
#define WCAP   768             // per-warp SMEM candidate buffer
#define FULLM  0xffffffffu

__device__ float g_rowloss[BMAX];

// Warp-collective in-place compaction of wbuf[0..cnt) keeping v > thr.
__device__ __forceinline__ int warp_prune(float* wbuf, int cnt, float thr,
                                          int lane, unsigned lmask)
{
    int newcnt = 0;
    int bound = (cnt + 31) & ~31;
    for (int i = lane; i < bound; i += 32) {
        float v = (i < cnt) ? wbuf[i] : -INFINITY;
        bool keep = v > thr;
        unsigned m = __ballot_sync(FULLM, keep);
        int p = newcnt + __popc(m & lmask);
        __syncwarp();
        if (keep) wbuf[p] = v;
        __syncwarp();
        newcnt += __popc(m);
    }
    return newcnt;
}

// Deterministic ballot deposit of one float4's elements above thr (raw X).
__device__ __forceinline__ void deposit4(const float4& x, float thr,
                                         float* wbuf, int& wcnt,
                                         int lane, unsigned lmask)
{
    unsigned m;
    m = __ballot_sync(FULLM, x.x > thr);
    if (x.x > thr) { int p = wcnt + __popc(m & lmask); if (p < WCAP) wbuf[p] = x.x; }
    wcnt += __popc(m);
    m = __ballot_sync(FULLM, x.y > thr);
    if (x.y > thr) { int p = wcnt + __popc(m & lmask); if (p < WCAP) wbuf[p] = x.y; }
    wcnt += __popc(m);
    m = __ballot_sync(FULLM, x.z > thr);
    if (x.z > thr) { int p = wcnt + __popc(m & lmask); if (p < WCAP) wbuf[p] = x.z; }
    wcnt += __popc(m);
    m = __ballot_sync(FULLM, x.w > thr);
    if (x.w > thr) { int p = wcnt + __popc(m & lmask); if (p < WCAP) wbuf[p] = x.w; }
    wcnt += __popc(m);
}

// ---------------------------------------------------------------------------
// Fused kernel: R5 streaming pass (unroll x2, MLP=4/warp, ballot deposits,
// clamped prunes) + in-block bisection over SMEM candidates + per-row loss.
// ---------------------------------------------------------------------------
__global__ __launch_bounds__(ATHR) void fused_kernel(
    const float* __restrict__ logits, const float* __restrict__ targets)
{
    __shared__ float s_wbuf[NWARP_A][WCAP];    // 24 KB
    __shared__ float s_m[NWARP_A], s_t[NWARP_A];
    __shared__ float s_bc[1];
    __shared__ float s_p0[NWARP_A], s_p1[NWARP_A], s_p2[NWARP_A];

    const int r     = blockIdx.x;
    const int t     = threadIdx.x;
    const int lane  = t & 31;
    const int wid   = t >> 5;
    const unsigned lmask = (1u << lane) - 1u;

    const float4* __restrict__ lg = reinterpret_cast<const float4*>(logits  + (size_t)r * VDIM);
    const float4* __restrict__ tg = reinterpret_cast<const float4*>(targets + (size_t)r * VDIM);

    float* wbuf = s_wbuf[wid];
    float  thr  = -INFINITY;      // running threshold in raw-X units (<= maxX-2)
    float  lmax = -INFINITY;      // lane-local running max of raw X
    float  tx0 = 0.0f, tx1 = 0.0f;
    int    wcnt = 0;
    int    it   = 0;

    // ==== Streaming pass (identical to R5's known-good loop) ====
    for (int j = t; j < NV4; j += 2 * ATHR, ++it) {
        const bool two = (j + ATHR < NV4);   // warp-uniform
        float4 xa = __ldcs(&lg[j]);
        float4 ta = __ldcs(&tg[j]);
        float4 xb = make_float4(-INFINITY, -INFINITY, -INFINITY, -INFINITY);
        float4 tb = make_float4(0.f, 0.f, 0.f, 0.f);
        if (two) {
            xb = __ldcs(&lg[j + ATHR]);
            tb = __ldcs(&tg[j + ATHR]);
        }

        float vma = fmaxf(fmaxf(xa.x, xa.y), fmaxf(xa.z, xa.w));
        float vmb = fmaxf(fmaxf(xb.x, xb.y), fmaxf(xb.z, xb.w));
        lmax = fmaxf(lmax, fmaxf(vma, vmb));

        tx0 = fmaf(ta.x, xa.x, tx0);
        tx1 = fmaf(ta.y, xa.y, tx1);
        tx0 = fmaf(ta.z, xa.z, tx0);
        tx1 = fmaf(ta.w, xa.w, tx1);
        if (two) {
            tx0 = fmaf(tb.x, xb.x, tx0);
            tx1 = fmaf(tb.y, xb.y, tx1);
            tx0 = fmaf(tb.z, xb.z, tx0);
            tx1 = fmaf(tb.w, xb.w, tx1);
        }

        // Safety prune (warp-uniform predicate; cnt CLAMPED before prune)
        if (wcnt > WCAP - 260) {
            int c = wcnt < WCAP ? wcnt : WCAP;
            wcnt = warp_prune(wbuf, c, thr, lane, lmask);
        }

        deposit4(xa, thr, wbuf, wcnt, lane, lmask);
        if (two) deposit4(xb, thr, wbuf, wcnt, lane, lmask);

        if (it < 4 || (it & 1)) {
            float wm = lmax;
            #pragma unroll
            for (int o = 16; o; o >>= 1)
                wm = fmaxf(wm, __shfl_xor_sync(FULLM, wm, o));
            thr = wm - 2.0f;
        }
    }

    // ==== Block reductions: exact row max (raw X), sum(t*X) ====
    float tx = tx0 + tx1;
    float wm = lmax;
    #pragma unroll
    for (int o = 16; o; o >>= 1) {
        wm = fmaxf(wm, __shfl_xor_sync(FULLM, wm, o));
        tx += __shfl_xor_sync(FULLM, tx, o);
    }
    if (lane == 0) { s_m[wid] = wm; s_t[wid] = tx; }
    __syncthreads();
    float rowTx = 0.0f;            // valid on t==0 only
    if (t == 0) {
        float m = s_m[0], s = s_t[0];
        for (int w = 1; w < NWARP_A; ++w) { m = fmaxf(m, s_m[w]); s += s_t[w]; }
        s_bc[0] = m;
        rowTx = s;
    }
    __syncthreads();
    const float rowmax = s_bc[0];
    const float thrF   = rowmax - 2.0f;   // raw-X exact candidate threshold

    // ==== Exact final filter (per-warp, clamped) ====
    {
        int c = wcnt < WCAP ? wcnt : WCAP;
        wcnt = warp_prune(wbuf, c, thrF, lane, lmask);
    }

    // ==== In-block bisection (all threads track identical tau state) ====
    // fmaf(0.5f, v, -tau) == (0.5f*v) - tau exactly (x0.5 is exact).
    const float mx     = 0.5f * rowmax;        // == reference max(Xs)
    float       tau_lo = mx - 1.0f;
    const float tau_hi = mx - 0.00559016994f;  // (1/32000)^(alpha-1), alpha=1.5
    float       dm     = tau_hi - tau_lo;

    // f_lo
    float part = 0.0f;
    for (int i = lane; i < wcnt; i += 32) {
        float d = fmaxf(fmaf(0.5f, wbuf[i], -tau_lo), 0.0f);
        part = fmaf(d, d, part);
    }
    #pragma unroll
    for (int o = 16; o; o >>= 1) part += __shfl_xor_sync(FULLM, part, o);
    if (lane == 0) s_p0[wid] = part;
    __syncthreads();
    if (t == 0) {
        float f = s_p0[0];
        for (int w = 1; w < NWARP_A; ++w) f += s_p0[w];
        s_bc[0] = f;
    }
    __syncthreads();
    const float f_lo = s_bc[0] - 1.0f;

    float tau_m = tau_lo;
    for (int itr = 0; itr < 50; ++itr) {
        dm *= 0.5f;
        tau_m = tau_lo + dm;
        if (tau_m == tau_lo) break;        // block-uniform: identical floats
        part = 0.0f;
        for (int i = lane; i < wcnt; i += 32) {
            float d = fmaxf(fmaf(0.5f, wbuf[i], -tau_m), 0.0f);
            part = fmaf(d, d, part);
        }
        #pragma unroll
        for (int o = 16; o; o >>= 1) part += __shfl_xor_sync(FULLM, part, o);
        if (lane == 0) s_p0[wid] = part;
        __syncthreads();
        if (t == 0) {
            float f = s_p0[0];
            for (int w = 1; w < NWARP_A; ++w) f += s_p0[w];
            s_bc[0] = f;
        }
        __syncthreads();
        float f_m = s_bc[0] - 1.0f;
        if (f_m * f_lo >= 0.0f) tau_lo = tau_m;   // identical in all threads
    }

    // ==== Final stats at last tau_m: s2=sum z^2, s3=sum z^3, sx=sum z^2*Xs ====
    float s2 = 0.0f, s3 = 0.0f, sxv = 0.0f;
    for (int i = lane; i < wcnt; i += 32) {
        float xs = 0.5f * wbuf[i];                 // exact
        float z  = fmaxf(xs - tau_m, 0.0f);
        float z2 = z * z;
        s2 += z2;
        s3  = fmaf(z2, z,  s3);
        sxv = fmaf(z2, xs, sxv);
    }
    #pragma unroll
    for (int o = 16; o; o >>= 1) {
        s2  += __shfl_xor_sync(FULLM, s2,  o);
        s3  += __shfl_xor_sync(FULLM, s3,  o);
        sxv += __shfl_xor_sync(FULLM, sxv, o);
    }
    if (lane == 0) { s_p0[wid] = s2; s_p1[wid] = s3; s_p2[wid] = sxv; }
    __syncthreads();
    if (t == 0) {
        float a2 = s_p0[0], a3 = s_p1[0], ax = s_p2[0];
        for (int w = 1; w < NWARP_A; ++w) {
            a2 += s_p0[w]; a3 += s_p1[w]; ax += s_p2[w];
        }
        // omega = (1 - sum(phat^1.5)) * 4/3, phat = z^2/a2
        float omega = (1.0f - a3 / (a2 * sqrtf(a2))) * (4.0f / 3.0f);
        g_rowloss[r] = omega + 2.0f * ax / a2 - rowTx;
    }
}

// ---------------------------------------------------------------------------
// Kernel 2: mean over rows (known-good).
// ---------------------------------------------------------------------------
__global__ void reduce_kernel(float* __restrict__ out, int B)
{
    __shared__ float s[1024];
    float a = 0.0f;
    for (int i = threadIdx.x; i < B; i += 1024) a += g_rowloss[i];
    s[threadIdx.x] = a;
    __syncthreads();
    #pragma unroll
    for (int o = 512; o; o >>= 1) {
        if (threadIdx.x < o) s[threadIdx.x] += s[threadIdx.x + o];
        __syncthreads();
    }
    if (threadIdx.x == 0) out[0] = s[0] / (float)B;
}

extern "C" void kernel_launch(void* const* d_in, const int* in_sizes, int n_in,
                              void* d_out, int out_size)
{
    const float* logits  = (const float*)d_in[0];
    const float* targets = (const float*)d_in[1];
    int B = in_sizes[0] / VDIM;
    if (B > BMAX) B = BMAX;

    fused_kernel<<<B, ATHR>>>(logits, targets);
    reduce_kernel<<<1, 1024>>>((float*)d_out, B);
}